// round 15
// baseline (speedup 1.0000x reference)
#include <cuda_runtime.h>
#include <cuda_fp16.h>
#include <stdint.h>
#include <math.h>

#define BQ 2
#define LQ 5000
#define NL (BQ*LQ)
#define RROWS (NL*8)
#define CIN 256
#define DLOI 128
#define NPTS0 32
#define NPTS1 8
#define HH 256
#define HALF 64
#define HW (HH*HH)
#define EPSBN 1e-5f

// ---------------- scratch (device globals; no allocation allowed) ----------------
__device__ __half g_xh[BQ * HW * DLOI];        // fc1 output, NHWC, fp16 (33.5 MB)
__device__ float g_wfc1T[CIN * DLOI];          // [k][o], tf32-rounded (fc1 B operand)
__device__ __half g_c1wH[HALF * DLOI];         // [o][k=c]
__device__ __half g_c2wH[HALF * 192];          // [o][k=dk*64+i]
__device__ __half g_c3wH[DLOI * HALF];         // [o][k=i]
__device__ __half g_wfc2H[4 * DLOI * NPTS1];   // [q][c*8+p] fp16
__device__ float g_bn1s[DLOI], g_bn1t[DLOI];
__device__ float g_bn2s[HALF], g_bn2t[HALF];
__device__ float g_bn3s[HALF], g_bn3t[HALF];
// line pipeline buffers (fp16)
__device__ __half g_h1h[RROWS * DLOI];         // bn1+relu(xp)
__device__ __half g_xph[RROWS * DLOI];         // raw pooled residual

__device__ __forceinline__ float to_tf32(float x) {
    uint32_t r;
    asm("cvt.rna.tf32.f32 %0, %1;" : "=r"(r) : "f"(x));
    return __uint_as_float(r);
}

// ---------------- prep: convert weights, fold BN ----------------
__global__ void prep_kernel(const float* __restrict__ w_fc1,
                            const float* __restrict__ bn1,
                            const float* __restrict__ c1w,
                            const float* __restrict__ bn2,
                            const float* __restrict__ c2w,
                            const float* __restrict__ bn3,
                            const float* __restrict__ c3w,
                            const float* __restrict__ wfc2)
{
    int t = blockIdx.x * blockDim.x + threadIdx.x;
    int stride = gridDim.x * blockDim.x;
    for (int idx = t; idx < DLOI * CIN; idx += stride) {
        int o = idx / CIN, k = idx % CIN;
        g_wfc1T[k * DLOI + o] = to_tf32(w_fc1[idx]);
    }
    for (int idx = t; idx < HALF * DLOI; idx += stride) {
        g_c1wH[idx] = __float2half_rn(c1w[idx]);
    }
    for (int idx = t; idx < HALF * HALF * 3; idx += stride) {
        int o = idx / (HALF * 3), rem = idx % (HALF * 3);
        int i = rem / 3, dk = rem % 3;
        g_c2wH[o * 192 + dk * HALF + i] = __float2half_rn(c2w[idx]);
    }
    for (int idx = t; idx < DLOI * HALF; idx += stride) {
        g_c3wH[idx] = __float2half_rn(c3w[idx]);
    }
    for (int idx = t; idx < 4 * DLOI * NPTS1; idx += stride) {
        g_wfc2H[idx] = __float2half_rn(wfc2[idx]);
    }
    for (int idx = t; idx < DLOI; idx += stride) {
        float g = bn1[idx], be = bn1[DLOI + idx], mu = bn1[2*DLOI + idx], va = bn1[3*DLOI + idx];
        float s = g * rsqrtf(va + EPSBN);
        g_bn1s[idx] = s; g_bn1t[idx] = be - mu * s;
    }
    for (int idx = t; idx < HALF; idx += stride) {
        float g = bn2[idx], be = bn2[HALF + idx], mu = bn2[2*HALF + idx], va = bn2[3*HALF + idx];
        float s = g * rsqrtf(va + EPSBN);
        g_bn2s[idx] = s; g_bn2t[idx] = be - mu * s;
        float g3 = bn3[idx], be3 = bn3[HALF + idx], mu3 = bn3[2*HALF + idx], va3 = bn3[3*HALF + idx];
        float s3 = g3 * rsqrtf(va3 + EPSBN);
        g_bn3s[idx] = s3; g_bn3t[idx] = be3 - mu3 * s3;
    }
}

// ---------------- MMA helpers ----------------
__device__ __forceinline__ void cp_async16(void* smem_ptr, const void* gmem_ptr) {
    uint32_t s = (uint32_t)__cvta_generic_to_shared(smem_ptr);
    asm volatile("cp.async.cg.shared.global [%0], [%1], 16;\n" :: "r"(s), "l"(gmem_ptr));
}

__device__ __forceinline__ void mma_tf32(float4& d, const float* a, const float* b) {
    asm volatile(
        "mma.sync.aligned.m16n8k8.row.col.f32.tf32.tf32.f32 "
        "{%0,%1,%2,%3}, {%4,%5,%6,%7}, {%8,%9}, {%0,%1,%2,%3};\n"
        : "+f"(d.x), "+f"(d.y), "+f"(d.z), "+f"(d.w)
        : "r"(__float_as_uint(a[0])), "r"(__float_as_uint(a[1])),
          "r"(__float_as_uint(a[2])), "r"(__float_as_uint(a[3])),
          "r"(__float_as_uint(b[0])), "r"(__float_as_uint(b[1])));
}

__device__ __forceinline__ void mma_f16(float4& d, const uint32_t* a, const uint32_t* b) {
    asm volatile(
        "mma.sync.aligned.m16n8k16.row.col.f32.f16.f16.f32 "
        "{%0,%1,%2,%3}, {%4,%5,%6,%7}, {%8,%9}, {%0,%1,%2,%3};\n"
        : "+f"(d.x), "+f"(d.y), "+f"(d.z), "+f"(d.w)
        : "r"(a[0]), "r"(a[1]), "r"(a[2]), "r"(a[3]), "r"(b[0]), "r"(b[1]));
}

__device__ __forceinline__ uint32_t lds_u32(const __half* p) {
    return *(const uint32_t*)p;
}
__device__ __forceinline__ uint32_t ldg_u32(const __half* p) {
    return __ldg((const uint32_t*)p);
}

// ---------------- fc1 GEMM: BM=256 x BN=128, tf32 mma.sync + cp.async ----------
#define KT 32
#define ASTR 260
#define BSTR 132
#define OSH 136
#define STAGE_FLOATS (KT * ASTR + KT * BSTR)
#define FC1_SMEM (2 * STAGE_FLOATS * 4)

__global__ __launch_bounds__(256) void fc1_gemm_tf32(const float* __restrict__ feat,
                                                     const float* __restrict__ bfc1)
{
    extern __shared__ float sm[];

    int b  = blockIdx.y;
    int p0 = blockIdx.x * 256;
    const float* A = feat + (size_t)b * CIN * HW;
    __half* O = g_xh + (size_t)b * HW * DLOI;

    int t    = threadIdx.x;
    int w    = t >> 5;
    int lane = t & 31;
    int g    = lane >> 2;
    int tg   = lane & 3;
    int warp_m = w & 3;
    int warp_n = w >> 2;
    int m_base = warp_m * 64;
    int n_base = warp_n * 64;

    float4 acc[4][8];
#pragma unroll
    for (int mi = 0; mi < 4; mi++)
#pragma unroll
        for (int ni = 0; ni < 8; ni++) acc[mi][ni] = make_float4(0.f, 0.f, 0.f, 0.f);

    auto issue_stage = [&](int s) {
        float* As = sm + (s & 1) * STAGE_FLOATS;
        float* Bs = As + KT * ASTR;
        int k0 = s * KT;
#pragma unroll
        for (int i = 0; i < 8; i++) {
            int f  = t + 256 * i;
            int kk = f >> 6;
            int pm = (f & 63) * 4;
            cp_async16(&As[kk * ASTR + pm], &A[(size_t)(k0 + kk) * HW + p0 + pm]);
        }
#pragma unroll
        for (int i = 0; i < 4; i++) {
            int f  = t + 256 * i;
            int kk = f >> 5;
            int pm = (f & 31) * 4;
            cp_async16(&Bs[kk * BSTR + pm], &g_wfc1T[(k0 + kk) * DLOI + pm]);
        }
        asm volatile("cp.async.commit_group;\n");
    };

    issue_stage(0);

    const int NS = CIN / KT;
    for (int s = 0; s < NS; s++) {
        if (s + 1 < NS) {
            issue_stage(s + 1);
            asm volatile("cp.async.wait_group 1;\n");
        } else {
            asm volatile("cp.async.wait_group 0;\n");
        }
        __syncthreads();

        float* As = sm + (s & 1) * STAGE_FLOATS;
        float* Bs = As + KT * ASTR;

#pragma unroll
        for (int ks = 0; ks < KT / 8; ks++) {
            int kb = ks * 8;
            float afr[4][4];
#pragma unroll
            for (int mi = 0; mi < 4; mi++) {
                int r = m_base + mi * 16 + g;
                afr[mi][0] = As[(kb + tg) * ASTR + r];
                afr[mi][1] = As[(kb + tg) * ASTR + r + 8];
                afr[mi][2] = As[(kb + tg + 4) * ASTR + r];
                afr[mi][3] = As[(kb + tg + 4) * ASTR + r + 8];
            }
            float bfr[8][2];
#pragma unroll
            for (int ni = 0; ni < 8; ni++) {
                int c = n_base + ni * 8 + g;
                bfr[ni][0] = Bs[(kb + tg) * BSTR + c];
                bfr[ni][1] = Bs[(kb + tg + 4) * BSTR + c];
            }
#pragma unroll
            for (int mi = 0; mi < 4; mi++)
#pragma unroll
                for (int ni = 0; ni < 8; ni++)
                    mma_tf32(acc[mi][ni], afr[mi], bfr[ni]);
        }
        __syncthreads();
    }

    float bx[8], by[8];
#pragma unroll
    for (int ni = 0; ni < 8; ni++) {
        int c = n_base + ni * 8 + 2 * tg;
        bx[ni] = bfc1[c];
        by[ni] = bfc1[c + 1];
    }

    __half* Osm = (__half*)sm;
#pragma unroll
    for (int chunk = 0; chunk < 4; chunk++) {
        if (warp_m == chunk) {
#pragma unroll
            for (int mi = 0; mi < 4; mi++) {
#pragma unroll
                for (int ni = 0; ni < 8; ni++) {
                    int row = mi * 16 + g;
                    int col = n_base + ni * 8 + 2 * tg;
                    float4 d = acc[mi][ni];
                    *(__half2*)&Osm[row * OSH + col] =
                        __floats2half2_rn(d.x + bx[ni], d.y + by[ni]);
                    *(__half2*)&Osm[(row + 8) * OSH + col] =
                        __floats2half2_rn(d.z + bx[ni], d.w + by[ni]);
                }
            }
        }
        __syncthreads();
#pragma unroll
        for (int i = 0; i < 4; i++) {
            int f   = t + 256 * i;
            int row = f >> 4;
            int h0  = (f & 15) * 8;
            uint4 v = *(const uint4*)&Osm[row * OSH + h0];
            *(uint4*)&O[(size_t)(p0 + chunk * 64 + row) * DLOI + h0] = v;
        }
        __syncthreads();
    }
}

// ---------------- line_gather: geometry + bilinear + maxpool -> g_h1h, g_xph ----
__global__ __launch_bounds__(128) void line_gather(const float* __restrict__ lines)
{
    __shared__ int4   soff[NPTS0];
    __shared__ float4 swt[NPTS0];

    int n = blockIdx.x;
    int t = threadIdx.x;
    int b = n / LQ;

    if (t < NPTS0) {
        const float* ln = lines + (size_t)n * 4;
        float ax = __ldg(ln), ay = __ldg(ln + 1), bx = __ldg(ln + 2), by = __ldg(ln + 3);
        float lam = (float)t * (1.0f / 31.0f);
        float px = ax * lam + bx * (1.0f - lam) - 0.5f;
        float py = ay * lam + by * (1.0f - lam) - 0.5f;
        float px0 = fminf(fmaxf(floorf(px), 0.0f), 255.0f);
        float py0 = fminf(fmaxf(floorf(py), 0.0f), 255.0f);
        float px1 = fminf(px0 + 1.0f, 255.0f);
        float py1 = fminf(py0 + 1.0f, 255.0f);
        int i0 = (int)px0, j0 = (int)py0, i1 = (int)px1, j1 = (int)py1;
        float w00 = (px1 - px) * (py1 - py);
        float w10 = (px - px0) * (py1 - py);
        float w01 = (px1 - px) * (py - py0);
        float w11 = (px - px0) * (py - py0);
        soff[t] = make_int4(((i0 << 8) + j0) << 6, ((i1 << 8) + j0) << 6,
                            ((i0 << 8) + j1) << 6, ((i1 << 8) + j1) << 6);
        swt[t] = make_float4(w00, w10, w01, w11);
    }
    __syncthreads();

    int c2 = t & 63, ph = t >> 6;
    const __half2* X2 = (const __half2*)g_xh + (size_t)b * HW * 64 + c2;

    int ca = 2 * c2, cb = 2 * c2 + 1;
    float sa = g_bn1s[ca], ta = g_bn1t[ca];
    float sb = g_bn1s[cb], tb = g_bn1t[cb];

#pragma unroll
    for (int pp = 0; pp < 4; pp++) {
        float2 m = make_float2(-INFINITY, -INFINITY);
#pragma unroll
        for (int kk = 0; kk < 4; kk++) {
            int k = (ph * 4 + pp) * 4 + kk;
            int4  o4 = soff[k];
            float4 w4 = swt[k];
            float2 h00 = __half22float2(__ldg(X2 + o4.x));
            float2 h10 = __half22float2(__ldg(X2 + o4.y));
            float2 h01 = __half22float2(__ldg(X2 + o4.z));
            float2 h11 = __half22float2(__ldg(X2 + o4.w));
            float vx = h00.x * w4.x + h10.x * w4.y + h01.x * w4.z + h11.x * w4.w;
            float vy = h00.y * w4.x + h10.y * w4.y + h01.y * w4.z + h11.y * w4.w;
            m.x = fmaxf(m.x, vx);
            m.y = fmaxf(m.y, vy);
        }
        int p = ph * 4 + pp;
        size_t base = ((size_t)n * 8 + p) * DLOI + ca;
        *(__half2*)&g_xph[base] = __floats2half2_rn(m.x, m.y);
        *(__half2*)&g_h1h[base] = __floats2half2_rn(
            fmaxf(m.x * sa + ta, 0.f), fmaxf(m.y * sb + tb, 0.f));
    }
}

// ---------------- fused bottleneck + fc2 + softmax: 64 rows (8 lines) per CTA ----
// smem layout (halves):
//  Asm [64][136] 8704  (phase1 A; later h3s [64][72])
//  h2s [80][72]  5760
//  ys  [8][1024] 8192
//  wfh [4096]    4096
// weights (c1w/c2w/c3w) are read as fragments directly from gmem (L2-resident).
#define FB_A    0
#define FB_H2   8704
#define FB_YS   (FB_H2 + 5760)
#define FB_WF   (FB_YS + 8192)
#define FB_TOT  (FB_WF + 4096)
#define FB_SMEM (FB_TOT * 2)

__global__ __launch_bounds__(256) void bottleneck_fused(const float* __restrict__ c1b,
                                                        const float* __restrict__ c2b,
                                                        const float* __restrict__ c3b,
                                                        const float* __restrict__ bfc2,
                                                        float* __restrict__ out)
{
    extern __shared__ __half smh[];
    __half* Asm  = smh + FB_A;     // stride 136 (phase1); h3s alias stride 72
    __half* h2s  = smh + FB_H2;    // stride 72, 80 rows (10 per line, pads 0&9)
    __half* ys   = smh + FB_YS;    // [8][1024]
    __half* wfh  = smh + FB_WF;    // linear 4096
    __half* h3s  = smh + FB_A;     // alias of Asm

    int r0 = blockIdx.x * 64;
    int t = threadIdx.x;
    int w = t >> 5, lane = t & 31, g = lane >> 2, tg = lane & 3;
    int m_base = (w & 3) * 16;
    int lb = m_base >> 3;          // rows m_base+g -> line lb (p=g); rows +8 -> line lb+1

    // ---- stage A + wfc2 only ----
#pragma unroll
    for (int i = 0; i < 4; i++) {          // A: 64 x 16 chunks
        int f = t + 256 * i;
        int row = f >> 4, c8 = (f & 15) * 8;
        cp_async16(&Asm[row * 136 + c8], &g_h1h[(size_t)(r0 + row) * DLOI + c8]);
    }
#pragma unroll
    for (int i = 0; i < 2; i++) {          // wfc2: 512 chunks
        int f = t + 256 * i;
        cp_async16(&wfh[f * 8], &g_wfc2H[f * 8]);
    }
    asm volatile("cp.async.commit_group;\n");

    // zero h2s pad rows (16 rows x 72 halves = 576 u32)
    for (int i = t; i < 576; i += 256) {
        int pr = i / 36, word = i % 36;
        int q = (pr >> 1) * 10 + (pr & 1) * 9;
        ((uint32_t*)&h2s[q * 72])[word] = 0;
    }
    asm volatile("cp.async.wait_group 0;\n");
    __syncthreads();

    // ---- phase 1: c1  M64 K128 N64 -> h2s (B frags from gmem) ----
    {
        int n_base = (w >> 2) * 32;
        float4 acc[4];
#pragma unroll
        for (int ni = 0; ni < 4; ni++) acc[ni] = make_float4(0.f,0.f,0.f,0.f);
#pragma unroll
        for (int ks = 0; ks < 8; ks++) {
            int kb = ks * 16;
            uint32_t afr[4];
            int r = m_base + g;
            afr[0] = lds_u32(&Asm[r * 136 + kb + 2*tg]);
            afr[1] = lds_u32(&Asm[(r + 8) * 136 + kb + 2*tg]);
            afr[2] = lds_u32(&Asm[r * 136 + kb + 2*tg + 8]);
            afr[3] = lds_u32(&Asm[(r + 8) * 136 + kb + 2*tg + 8]);
            uint32_t bfr[4][2];
#pragma unroll
            for (int ni = 0; ni < 4; ni++) {
                int c = n_base + ni * 8 + g;
                bfr[ni][0] = ldg_u32(&g_c1wH[c * DLOI + kb + 2*tg]);
                bfr[ni][1] = ldg_u32(&g_c1wH[c * DLOI + kb + 2*tg + 8]);
            }
#pragma unroll
            for (int ni = 0; ni < 4; ni++)
                mma_f16(acc[ni], afr, bfr[ni]);
        }
        int q1 = lb * 10 + g + 1;
        int q2 = (lb + 1) * 10 + g + 1;
#pragma unroll
        for (int ni = 0; ni < 4; ni++) {
            int o0 = n_base + ni * 8 + 2 * tg, o1 = o0 + 1;
            float bia0 = __ldg(&c1b[o0]), bia1 = __ldg(&c1b[o1]);
            float s0 = g_bn2s[o0], t0 = g_bn2t[o0];
            float s1 = g_bn2s[o1], t1 = g_bn2t[o1];
            float4 d = acc[ni];
            h2s[q1 * 72 + o0] = __float2half_rn(fmaxf((d.x + bia0) * s0 + t0, 0.f));
            h2s[q1 * 72 + o1] = __float2half_rn(fmaxf((d.y + bia1) * s1 + t1, 0.f));
            h2s[q2 * 72 + o0] = __float2half_rn(fmaxf((d.z + bia0) * s0 + t0, 0.f));
            h2s[q2 * 72 + o1] = __float2half_rn(fmaxf((d.w + bia1) * s1 + t1, 0.f));
        }
    }
    __syncthreads();

    // ---- phase 2: c2  M64 K192 N64 -> h3s (aliases Asm; B frags from gmem) ----
    {
        int n_base = (w >> 2) * 32;
        float4 acc[4];
#pragma unroll
        for (int ni = 0; ni < 4; ni++) acc[ni] = make_float4(0.f,0.f,0.f,0.f);
#pragma unroll
        for (int ks = 0; ks < 12; ks++) {
            int kb = ks * 16;
            int dk = kb >> 6, koff = kb & 63;
            int qa = lb * 10 + g + dk;
            int qb = (lb + 1) * 10 + g + dk;
            uint32_t afr[4];
            afr[0] = lds_u32(&h2s[qa * 72 + koff + 2*tg]);
            afr[1] = lds_u32(&h2s[qb * 72 + koff + 2*tg]);
            afr[2] = lds_u32(&h2s[qa * 72 + koff + 2*tg + 8]);
            afr[3] = lds_u32(&h2s[qb * 72 + koff + 2*tg + 8]);
            uint32_t bfr[4][2];
#pragma unroll
            for (int ni = 0; ni < 4; ni++) {
                int c = n_base + ni * 8 + g;
                bfr[ni][0] = ldg_u32(&g_c2wH[c * 192 + kb + 2*tg]);
                bfr[ni][1] = ldg_u32(&g_c2wH[c * 192 + kb + 2*tg + 8]);
            }
#pragma unroll
            for (int ni = 0; ni < 4; ni++)
                mma_f16(acc[ni], afr, bfr[ni]);
        }
        __syncthreads();   // all Asm/h2s reads complete before h3s overwrites Asm
        int r = m_base + g;
#pragma unroll
        for (int ni = 0; ni < 4; ni++) {
            int o0 = n_base + ni * 8 + 2 * tg, o1 = o0 + 1;
            float bia0 = __ldg(&c2b[o0]), bia1 = __ldg(&c2b[o1]);
            float s0 = g_bn3s[o0], t0 = g_bn3t[o0];
            float s1 = g_bn3s[o1], t1 = g_bn3t[o1];
            float4 d = acc[ni];
            h3s[r * 72 + o0] = __float2half_rn(fmaxf((d.x + bia0) * s0 + t0, 0.f));
            h3s[r * 72 + o1] = __float2half_rn(fmaxf((d.y + bia1) * s1 + t1, 0.f));
            h3s[(r + 8) * 72 + o0] = __float2half_rn(fmaxf((d.z + bia0) * s0 + t0, 0.f));
            h3s[(r + 8) * 72 + o1] = __float2half_rn(fmaxf((d.w + bia1) * s1 + t1, 0.f));
        }
    }
    __syncthreads();

    // ---- phase 3: c3  M64 K64 N128 + residual + relu -> ys (B frags from gmem) ----
    {
        int n_base = (w >> 2) * 64;
        float4 acc[8];
#pragma unroll
        for (int ni = 0; ni < 8; ni++) acc[ni] = make_float4(0.f,0.f,0.f,0.f);
#pragma unroll
        for (int ks = 0; ks < 4; ks++) {
            int kb = ks * 16;
            uint32_t afr[4];
            int r = m_base + g;
            afr[0] = lds_u32(&h3s[r * 72 + kb + 2*tg]);
            afr[1] = lds_u32(&h3s[(r + 8) * 72 + kb + 2*tg]);
            afr[2] = lds_u32(&h3s[r * 72 + kb + 2*tg + 8]);
            afr[3] = lds_u32(&h3s[(r + 8) * 72 + kb + 2*tg + 8]);
            uint32_t bfr[8][2];
#pragma unroll
            for (int ni = 0; ni < 8; ni++) {
                int c = n_base + ni * 8 + g;
                bfr[ni][0] = ldg_u32(&g_c3wH[c * HALF + kb + 2*tg]);
                bfr[ni][1] = ldg_u32(&g_c3wH[c * HALF + kb + 2*tg + 8]);
            }
#pragma unroll
            for (int ni = 0; ni < 8; ni++)
                mma_f16(acc[ni], afr, bfr[ni]);
        }
        int r = m_base + g, r2 = r + 8;
        int l1 = lb, p1 = g;
        int l2 = lb + 1, p2 = g;
        size_t gr1 = (size_t)(r0 + r) * DLOI, gr2 = (size_t)(r0 + r2) * DLOI;
#pragma unroll
        for (int ni = 0; ni < 8; ni++) {
            int o0 = n_base + ni * 8 + 2 * tg, o1 = o0 + 1;
            float bia0 = __ldg(&c3b[o0]), bia1 = __ldg(&c3b[o1]);
            float4 d = acc[ni];
            ys[l1 * 1024 + o0 * 8 + p1] = __float2half_rn(
                fmaxf(d.x + bia0 + __half2float(__ldg(&g_xph[gr1 + o0])), 0.f));
            ys[l1 * 1024 + o1 * 8 + p1] = __float2half_rn(
                fmaxf(d.y + bia1 + __half2float(__ldg(&g_xph[gr1 + o1])), 0.f));
            ys[l2 * 1024 + o0 * 8 + p2] = __float2half_rn(
                fmaxf(d.z + bia0 + __half2float(__ldg(&g_xph[gr2 + o0])), 0.f));
            ys[l2 * 1024 + o1 * 8 + p2] = __float2half_rn(
                fmaxf(d.w + bia1 + __half2float(__ldg(&g_xph[gr2 + o1])), 0.f));
        }
    }
    __syncthreads();

    // ---- phase 4: fc2 + softmax, warp per line ----
    {
        const __half* Y = ys + w * 1024;
        float s0 = 0.f, s1 = 0.f, s2 = 0.f, s3 = 0.f;
#pragma unroll
        for (int j = 0; j < 8; j++) {
            int idx = lane * 4 + j * 128;
            float2 ya = __half22float2(*(const __half2*)&Y[idx]);
            float2 yb = __half22float2(*(const __half2*)&Y[idx + 2]);
            float2 w0a = __half22float2(*(const __half2*)&wfh[idx]);
            float2 w0b = __half22float2(*(const __half2*)&wfh[idx + 2]);
            float2 w1a = __half22float2(*(const __half2*)&wfh[1024 + idx]);
            float2 w1b = __half22float2(*(const __half2*)&wfh[1024 + idx + 2]);
            float2 w2a = __half22float2(*(const __half2*)&wfh[2048 + idx]);
            float2 w2b = __half22float2(*(const __half2*)&wfh[2048 + idx + 2]);
            float2 w3a = __half22float2(*(const __half2*)&wfh[3072 + idx]);
            float2 w3b = __half22float2(*(const __half2*)&wfh[3072 + idx + 2]);
            s0 += ya.x * w0a.x + ya.y * w0a.y + yb.x * w0b.x + yb.y * w0b.y;
            s1 += ya.x * w1a.x + ya.y * w1a.y + yb.x * w1b.x + yb.y * w1b.y;
            s2 += ya.x * w2a.x + ya.y * w2a.y + yb.x * w2b.x + yb.y * w2b.y;
            s3 += ya.x * w3a.x + ya.y * w3a.y + yb.x * w3b.x + yb.y * w3b.y;
        }
#pragma unroll
        for (int off = 16; off; off >>= 1) {
            s0 += __shfl_down_sync(0xffffffffu, s0, off);
            s1 += __shfl_down_sync(0xffffffffu, s1, off);
            s2 += __shfl_down_sync(0xffffffffu, s2, off);
            s3 += __shfl_down_sync(0xffffffffu, s3, off);
        }
        if (lane == 0) {
            int n = blockIdx.x * 8 + w;
            float z0 = s0 + __ldg(&bfc2[0]), z1 = s1 + __ldg(&bfc2[1]);
            float z2 = s2 + __ldg(&bfc2[2]), z3 = s3 + __ldg(&bfc2[3]);
            float m = fmaxf(fmaxf(z0, z1), fmaxf(z2, z3));
            float e0 = expf(z0 - m), e1 = expf(z1 - m), e2 = expf(z2 - m), e3 = expf(z3 - m);
            float inv = 1.0f / (e0 + e1 + e2 + e3);
            *(float4*)&out[(size_t)n * 4] = make_float4(e0 * inv, e1 * inv, e2 * inv, e3 * inv);
        }
    }
}

// ---------------- launch ----------------
extern "C" void kernel_launch(void* const* d_in, const int* in_sizes, int n_in,
                              void* d_out, int out_size)
{
    const float* feature = (const float*)d_in[0];
    const float* lines   = (const float*)d_in[1];
    const float* w_fc1   = (const float*)d_in[2];
    const float* b_fc1   = (const float*)d_in[3];
    const float* bn1     = (const float*)d_in[4];
    const float* c1_w    = (const float*)d_in[5];
    const float* c1_b    = (const float*)d_in[6];
    const float* bn2     = (const float*)d_in[7];
    const float* c2_w    = (const float*)d_in[8];
    const float* c2_b    = (const float*)d_in[9];
    const float* bn3     = (const float*)d_in[10];
    const float* c3_w    = (const float*)d_in[11];
    const float* c3_b    = (const float*)d_in[12];
    const float* w_fc2   = (const float*)d_in[13];
    const float* b_fc2   = (const float*)d_in[14];
    float* out = (float*)d_out;

    static int attr_set = 0;
    if (!attr_set) {
        cudaFuncSetAttribute(fc1_gemm_tf32, cudaFuncAttributeMaxDynamicSharedMemorySize, FC1_SMEM);
        cudaFuncSetAttribute(bottleneck_fused, cudaFuncAttributeMaxDynamicSharedMemorySize, FB_SMEM);
        attr_set = 1;
    }

    prep_kernel<<<64, 256>>>(w_fc1, bn1, c1_w, bn2, c2_w, bn3, c3_w, w_fc2);

    dim3 grid(HW / 256, BQ);
    fc1_gemm_tf32<<<grid, 256, FC1_SMEM>>>(feature, b_fc1);

    line_gather<<<NL, 128>>>(lines);
    bottleneck_fused<<<RROWS / 64, 256, FB_SMEM>>>(c1_b, c2_b, c3_b, b_fc2, out);
}

// round 16
// speedup vs baseline: 1.3333x; 1.3333x over previous
#include <cuda_runtime.h>
#include <cuda_fp16.h>
#include <stdint.h>
#include <math.h>

#define BQ 2
#define LQ 5000
#define NL (BQ*LQ)
#define RROWS (NL*8)
#define CIN 256
#define DLOI 128
#define NPTS0 32
#define NPTS1 8
#define HH 256
#define HALF 64
#define HW (HH*HH)
#define EPSBN 1e-5f

// ---------------- scratch (device globals; no allocation allowed) ----------------
__device__ __half g_xh[BQ * HW * DLOI];        // fc1 output, NHWC, fp16 (33.5 MB)
__device__ float g_wfc1T[CIN * DLOI];          // [k][o], tf32-rounded (fc1 B operand)
__device__ __half g_c1wH[HALF * DLOI];         // [o][k=c]
__device__ __half g_c2wH[HALF * 192];          // [o][k=dk*64+i]
__device__ __half g_c3wH[DLOI * HALF];         // [o][k=i]
__device__ __half g_wfc2H[4 * DLOI * NPTS1];   // [q][c*8+p] fp16
__device__ float g_bn1s[DLOI], g_bn1t[DLOI];
__device__ float g_bn2s[HALF], g_bn2t[HALF];
__device__ float g_bn3s[HALF], g_bn3t[HALF];
// line pipeline buffers (fp16)
__device__ __half g_h1h[RROWS * DLOI];         // bn1+relu(xp)
__device__ __half g_xph[RROWS * DLOI];         // raw pooled residual

__device__ __forceinline__ float to_tf32(float x) {
    uint32_t r;
    asm("cvt.rna.tf32.f32 %0, %1;" : "=r"(r) : "f"(x));
    return __uint_as_float(r);
}

// ---------------- prep: convert weights, fold BN ----------------
__global__ void prep_kernel(const float* __restrict__ w_fc1,
                            const float* __restrict__ bn1,
                            const float* __restrict__ c1w,
                            const float* __restrict__ bn2,
                            const float* __restrict__ c2w,
                            const float* __restrict__ bn3,
                            const float* __restrict__ c3w,
                            const float* __restrict__ wfc2)
{
    int t = blockIdx.x * blockDim.x + threadIdx.x;
    int stride = gridDim.x * blockDim.x;
    for (int idx = t; idx < DLOI * CIN; idx += stride) {
        int o = idx / CIN, k = idx % CIN;
        g_wfc1T[k * DLOI + o] = to_tf32(w_fc1[idx]);
    }
    for (int idx = t; idx < HALF * DLOI; idx += stride) {
        g_c1wH[idx] = __float2half_rn(c1w[idx]);
    }
    for (int idx = t; idx < HALF * HALF * 3; idx += stride) {
        int o = idx / (HALF * 3), rem = idx % (HALF * 3);
        int i = rem / 3, dk = rem % 3;
        g_c2wH[o * 192 + dk * HALF + i] = __float2half_rn(c2w[idx]);
    }
    for (int idx = t; idx < DLOI * HALF; idx += stride) {
        g_c3wH[idx] = __float2half_rn(c3w[idx]);
    }
    for (int idx = t; idx < 4 * DLOI * NPTS1; idx += stride) {
        g_wfc2H[idx] = __float2half_rn(wfc2[idx]);
    }
    for (int idx = t; idx < DLOI; idx += stride) {
        float g = bn1[idx], be = bn1[DLOI + idx], mu = bn1[2*DLOI + idx], va = bn1[3*DLOI + idx];
        float s = g * rsqrtf(va + EPSBN);
        g_bn1s[idx] = s; g_bn1t[idx] = be - mu * s;
    }
    for (int idx = t; idx < HALF; idx += stride) {
        float g = bn2[idx], be = bn2[HALF + idx], mu = bn2[2*HALF + idx], va = bn2[3*HALF + idx];
        float s = g * rsqrtf(va + EPSBN);
        g_bn2s[idx] = s; g_bn2t[idx] = be - mu * s;
        float g3 = bn3[idx], be3 = bn3[HALF + idx], mu3 = bn3[2*HALF + idx], va3 = bn3[3*HALF + idx];
        float s3 = g3 * rsqrtf(va3 + EPSBN);
        g_bn3s[idx] = s3; g_bn3t[idx] = be3 - mu3 * s3;
    }
}

// ---------------- MMA helpers ----------------
__device__ __forceinline__ void cp_async16(void* smem_ptr, const void* gmem_ptr) {
    uint32_t s = (uint32_t)__cvta_generic_to_shared(smem_ptr);
    asm volatile("cp.async.cg.shared.global [%0], [%1], 16;\n" :: "r"(s), "l"(gmem_ptr));
}

__device__ __forceinline__ void mma_tf32(float4& d, const float* a, const float* b) {
    asm volatile(
        "mma.sync.aligned.m16n8k8.row.col.f32.tf32.tf32.f32 "
        "{%0,%1,%2,%3}, {%4,%5,%6,%7}, {%8,%9}, {%0,%1,%2,%3};\n"
        : "+f"(d.x), "+f"(d.y), "+f"(d.z), "+f"(d.w)
        : "r"(__float_as_uint(a[0])), "r"(__float_as_uint(a[1])),
          "r"(__float_as_uint(a[2])), "r"(__float_as_uint(a[3])),
          "r"(__float_as_uint(b[0])), "r"(__float_as_uint(b[1])));
}

__device__ __forceinline__ void mma_f16(float4& d, const uint32_t* a, const uint32_t* b) {
    asm volatile(
        "mma.sync.aligned.m16n8k16.row.col.f32.f16.f16.f32 "
        "{%0,%1,%2,%3}, {%4,%5,%6,%7}, {%8,%9}, {%0,%1,%2,%3};\n"
        : "+f"(d.x), "+f"(d.y), "+f"(d.z), "+f"(d.w)
        : "r"(a[0]), "r"(a[1]), "r"(a[2]), "r"(a[3]), "r"(b[0]), "r"(b[1]));
}

__device__ __forceinline__ uint32_t lds_u32(const __half* p) {
    return *(const uint32_t*)p;
}

// ---------------- fc1 GEMM: BM=256 x BN=128, tf32 mma.sync + cp.async ----------
#define KT 32
#define ASTR 260
#define BSTR 132
#define OSH 136
#define STAGE_FLOATS (KT * ASTR + KT * BSTR)
#define FC1_SMEM (2 * STAGE_FLOATS * 4)

__global__ __launch_bounds__(256) void fc1_gemm_tf32(const float* __restrict__ feat,
                                                     const float* __restrict__ bfc1)
{
    extern __shared__ float sm[];

    int b  = blockIdx.y;
    int p0 = blockIdx.x * 256;
    const float* A = feat + (size_t)b * CIN * HW;
    __half* O = g_xh + (size_t)b * HW * DLOI;

    int t    = threadIdx.x;
    int w    = t >> 5;
    int lane = t & 31;
    int g    = lane >> 2;
    int tg   = lane & 3;
    int warp_m = w & 3;
    int warp_n = w >> 2;
    int m_base = warp_m * 64;
    int n_base = warp_n * 64;

    float4 acc[4][8];
#pragma unroll
    for (int mi = 0; mi < 4; mi++)
#pragma unroll
        for (int ni = 0; ni < 8; ni++) acc[mi][ni] = make_float4(0.f, 0.f, 0.f, 0.f);

    auto issue_stage = [&](int s) {
        float* As = sm + (s & 1) * STAGE_FLOATS;
        float* Bs = As + KT * ASTR;
        int k0 = s * KT;
#pragma unroll
        for (int i = 0; i < 8; i++) {
            int f  = t + 256 * i;
            int kk = f >> 6;
            int pm = (f & 63) * 4;
            cp_async16(&As[kk * ASTR + pm], &A[(size_t)(k0 + kk) * HW + p0 + pm]);
        }
#pragma unroll
        for (int i = 0; i < 4; i++) {
            int f  = t + 256 * i;
            int kk = f >> 5;
            int pm = (f & 31) * 4;
            cp_async16(&Bs[kk * BSTR + pm], &g_wfc1T[(k0 + kk) * DLOI + pm]);
        }
        asm volatile("cp.async.commit_group;\n");
    };

    issue_stage(0);

    const int NS = CIN / KT;
    for (int s = 0; s < NS; s++) {
        if (s + 1 < NS) {
            issue_stage(s + 1);
            asm volatile("cp.async.wait_group 1;\n");
        } else {
            asm volatile("cp.async.wait_group 0;\n");
        }
        __syncthreads();

        float* As = sm + (s & 1) * STAGE_FLOATS;
        float* Bs = As + KT * ASTR;

#pragma unroll
        for (int ks = 0; ks < KT / 8; ks++) {
            int kb = ks * 8;
            float afr[4][4];
#pragma unroll
            for (int mi = 0; mi < 4; mi++) {
                int r = m_base + mi * 16 + g;
                afr[mi][0] = As[(kb + tg) * ASTR + r];
                afr[mi][1] = As[(kb + tg) * ASTR + r + 8];
                afr[mi][2] = As[(kb + tg + 4) * ASTR + r];
                afr[mi][3] = As[(kb + tg + 4) * ASTR + r + 8];
            }
            float bfr[8][2];
#pragma unroll
            for (int ni = 0; ni < 8; ni++) {
                int c = n_base + ni * 8 + g;
                bfr[ni][0] = Bs[(kb + tg) * BSTR + c];
                bfr[ni][1] = Bs[(kb + tg + 4) * BSTR + c];
            }
#pragma unroll
            for (int mi = 0; mi < 4; mi++)
#pragma unroll
                for (int ni = 0; ni < 8; ni++)
                    mma_tf32(acc[mi][ni], afr[mi], bfr[ni]);
        }
        __syncthreads();
    }

    float bx[8], by[8];
#pragma unroll
    for (int ni = 0; ni < 8; ni++) {
        int c = n_base + ni * 8 + 2 * tg;
        bx[ni] = bfc1[c];
        by[ni] = bfc1[c + 1];
    }

    __half* Osm = (__half*)sm;
#pragma unroll
    for (int chunk = 0; chunk < 4; chunk++) {
        if (warp_m == chunk) {
#pragma unroll
            for (int mi = 0; mi < 4; mi++) {
#pragma unroll
                for (int ni = 0; ni < 8; ni++) {
                    int row = mi * 16 + g;
                    int col = n_base + ni * 8 + 2 * tg;
                    float4 d = acc[mi][ni];
                    *(__half2*)&Osm[row * OSH + col] =
                        __floats2half2_rn(d.x + bx[ni], d.y + by[ni]);
                    *(__half2*)&Osm[(row + 8) * OSH + col] =
                        __floats2half2_rn(d.z + bx[ni], d.w + by[ni]);
                }
            }
        }
        __syncthreads();
#pragma unroll
        for (int i = 0; i < 4; i++) {
            int f   = t + 256 * i;
            int row = f >> 4;
            int h0  = (f & 15) * 8;
            uint4 v = *(const uint4*)&Osm[row * OSH + h0];
            *(uint4*)&O[(size_t)(p0 + chunk * 64 + row) * DLOI + h0] = v;
        }
        __syncthreads();
    }
}

// ---------------- line_gather: geometry + bilinear + maxpool -> g_h1h, g_xph ----
__global__ __launch_bounds__(128) void line_gather(const float* __restrict__ lines)
{
    __shared__ int4   soff[NPTS0];
    __shared__ float4 swt[NPTS0];

    int n = blockIdx.x;
    int t = threadIdx.x;
    int b = n / LQ;

    if (t < NPTS0) {
        const float* ln = lines + (size_t)n * 4;
        float ax = __ldg(ln), ay = __ldg(ln + 1), bx = __ldg(ln + 2), by = __ldg(ln + 3);
        float lam = (float)t * (1.0f / 31.0f);
        float px = ax * lam + bx * (1.0f - lam) - 0.5f;
        float py = ay * lam + by * (1.0f - lam) - 0.5f;
        float px0 = fminf(fmaxf(floorf(px), 0.0f), 255.0f);
        float py0 = fminf(fmaxf(floorf(py), 0.0f), 255.0f);
        float px1 = fminf(px0 + 1.0f, 255.0f);
        float py1 = fminf(py0 + 1.0f, 255.0f);
        int i0 = (int)px0, j0 = (int)py0, i1 = (int)px1, j1 = (int)py1;
        float w00 = (px1 - px) * (py1 - py);
        float w10 = (px - px0) * (py1 - py);
        float w01 = (px1 - px) * (py - py0);
        float w11 = (px - px0) * (py - py0);
        soff[t] = make_int4(((i0 << 8) + j0) << 6, ((i1 << 8) + j0) << 6,
                            ((i0 << 8) + j1) << 6, ((i1 << 8) + j1) << 6);
        swt[t] = make_float4(w00, w10, w01, w11);
    }
    __syncthreads();

    int c2 = t & 63, ph = t >> 6;
    const __half2* X2 = (const __half2*)g_xh + (size_t)b * HW * 64 + c2;

    int ca = 2 * c2, cb = 2 * c2 + 1;
    float sa = g_bn1s[ca], ta = g_bn1t[ca];
    float sb = g_bn1s[cb], tb = g_bn1t[cb];

#pragma unroll
    for (int pp = 0; pp < 4; pp++) {
        float2 m = make_float2(-INFINITY, -INFINITY);
#pragma unroll
        for (int kk = 0; kk < 4; kk++) {
            int k = (ph * 4 + pp) * 4 + kk;
            int4  o4 = soff[k];
            float4 w4 = swt[k];
            float2 h00 = __half22float2(__ldg(X2 + o4.x));
            float2 h10 = __half22float2(__ldg(X2 + o4.y));
            float2 h01 = __half22float2(__ldg(X2 + o4.z));
            float2 h11 = __half22float2(__ldg(X2 + o4.w));
            float vx = h00.x * w4.x + h10.x * w4.y + h01.x * w4.z + h11.x * w4.w;
            float vy = h00.y * w4.x + h10.y * w4.y + h01.y * w4.z + h11.y * w4.w;
            m.x = fmaxf(m.x, vx);
            m.y = fmaxf(m.y, vy);
        }
        int p = ph * 4 + pp;
        size_t base = ((size_t)n * 8 + p) * DLOI + ca;
        *(__half2*)&g_xph[base] = __floats2half2_rn(m.x, m.y);
        *(__half2*)&g_h1h[base] = __floats2half2_rn(
            fmaxf(m.x * sa + ta, 0.f), fmaxf(m.y * sb + tb, 0.f));
    }
}

// ---------------- fused bottleneck + fc2 + softmax: 64 rows (8 lines) per CTA ----
// smem (halves), phase-overlaid:
//  Asm [64][136] 8704  : phase1 A; phase2+ h3s [64][72]
//  h2s [80][72]  5760  : phase1/2 h2; phase4 wfh[4096]
//  W1  9216            : phase1 c1w [64][136]; phase3 c3w [128][72]
//  W2  12800           : phase2 c2w [64][200]; phase3+ ys [8][1024]
// total 36480 halves = 72960 B -> 3 CTAs/SM
#define FB_A    0
#define FB_H2   8704
#define FB_W1   (FB_H2 + 5760)
#define FB_W2   (FB_W1 + 9216)
#define FB_TOT  (FB_W2 + 12800)
#define FB_SMEM (FB_TOT * 2)

__global__ __launch_bounds__(256) void bottleneck_fused(const float* __restrict__ c1b,
                                                        const float* __restrict__ c2b,
                                                        const float* __restrict__ c3b,
                                                        const float* __restrict__ bfc2,
                                                        float* __restrict__ out)
{
    extern __shared__ __half smh[];
    __half* Asm  = smh + FB_A;
    __half* h2s  = smh + FB_H2;
    __half* c1ws = smh + FB_W1;    // stride 136
    __half* c3ws = smh + FB_W1;    // stride 72 (phase 3)
    __half* c2ws = smh + FB_W2;    // stride 200
    __half* ys   = smh + FB_W2;    // [8][1024] (phase 3+)
    __half* wfh  = smh + FB_H2;    // [4096] (phase 4)
    __half* h3s  = smh + FB_A;     // stride 72 (phase 2+)

    int r0 = blockIdx.x * 64;
    int t = threadIdx.x;
    int w = t >> 5, lane = t & 31, g = lane >> 2, tg = lane & 3;
    int m_base = (w & 3) * 16;
    int lb = m_base >> 3;

    // ---- G1: A + c1w ----
#pragma unroll
    for (int i = 0; i < 4; i++) {
        int f = t + 256 * i;
        int row = f >> 4, c8 = (f & 15) * 8;
        cp_async16(&Asm[row * 136 + c8], &g_h1h[(size_t)(r0 + row) * DLOI + c8]);
    }
#pragma unroll
    for (int i = 0; i < 4; i++) {
        int f = t + 256 * i;
        int row = f >> 4, c8 = (f & 15) * 8;
        cp_async16(&c1ws[row * 136 + c8], &g_c1wH[row * DLOI + c8]);
    }
    asm volatile("cp.async.commit_group;\n");
    // ---- G2: c2w ----
#pragma unroll
    for (int i = 0; i < 6; i++) {
        int f = t + 256 * i;
        int row = f / 24, c8 = (f % 24) * 8;
        cp_async16(&c2ws[row * 200 + c8], &g_c2wH[row * 192 + c8]);
    }
    asm volatile("cp.async.commit_group;\n");

    // zero h2s pad rows (16 rows x 72 halves = 576 u32)
    for (int i = t; i < 576; i += 256) {
        int pr = i / 36, word = i % 36;
        int q = (pr >> 1) * 10 + (pr & 1) * 9;
        ((uint32_t*)&h2s[q * 72])[word] = 0;
    }
    asm volatile("cp.async.wait_group 1;\n");   // G1 done
    __syncthreads();

    // ---- phase 1: c1  M64 K128 N64 -> h2s ----
    {
        int n_base = (w >> 2) * 32;
        float4 acc[4];
#pragma unroll
        for (int ni = 0; ni < 4; ni++) acc[ni] = make_float4(0.f,0.f,0.f,0.f);
#pragma unroll
        for (int ks = 0; ks < 8; ks++) {
            int kb = ks * 16;
            uint32_t afr[4];
            int r = m_base + g;
            afr[0] = lds_u32(&Asm[r * 136 + kb + 2*tg]);
            afr[1] = lds_u32(&Asm[(r + 8) * 136 + kb + 2*tg]);
            afr[2] = lds_u32(&Asm[r * 136 + kb + 2*tg + 8]);
            afr[3] = lds_u32(&Asm[(r + 8) * 136 + kb + 2*tg + 8]);
            uint32_t bfr[4][2];
#pragma unroll
            for (int ni = 0; ni < 4; ni++) {
                int c = n_base + ni * 8 + g;
                bfr[ni][0] = lds_u32(&c1ws[c * 136 + kb + 2*tg]);
                bfr[ni][1] = lds_u32(&c1ws[c * 136 + kb + 2*tg + 8]);
            }
#pragma unroll
            for (int ni = 0; ni < 4; ni++)
                mma_f16(acc[ni], afr, bfr[ni]);
        }
        int q1 = lb * 10 + g + 1;
        int q2 = (lb + 1) * 10 + g + 1;
#pragma unroll
        for (int ni = 0; ni < 4; ni++) {
            int o0 = n_base + ni * 8 + 2 * tg, o1 = o0 + 1;
            float bia0 = __ldg(&c1b[o0]), bia1 = __ldg(&c1b[o1]);
            float s0 = g_bn2s[o0], t0 = g_bn2t[o0];
            float s1 = g_bn2s[o1], t1 = g_bn2t[o1];
            float4 d = acc[ni];
            h2s[q1 * 72 + o0] = __float2half_rn(fmaxf((d.x + bia0) * s0 + t0, 0.f));
            h2s[q1 * 72 + o1] = __float2half_rn(fmaxf((d.y + bia1) * s1 + t1, 0.f));
            h2s[q2 * 72 + o0] = __float2half_rn(fmaxf((d.z + bia0) * s0 + t0, 0.f));
            h2s[q2 * 72 + o1] = __float2half_rn(fmaxf((d.w + bia1) * s1 + t1, 0.f));
        }
    }
    __syncthreads();   // h2s visible; c1w reads done -> W1 free

    // ---- G3: c3w into W1 (stride 72) ----
#pragma unroll
    for (int i = 0; i < 4; i++) {
        int f = t + 256 * i;             // 1024 chunks: 128 rows x 8
        int row = f >> 3, c8 = (f & 7) * 8;
        cp_async16(&c3ws[row * 72 + c8], &g_c3wH[row * HALF + c8]);
    }
    asm volatile("cp.async.commit_group;\n");
    asm volatile("cp.async.wait_group 1;\n");   // G2 (c2w) done
    __syncthreads();

    // ---- phase 2: c2  M64 K192 N64 ----
    {
        int n_base = (w >> 2) * 32;
        float4 acc[4];
#pragma unroll
        for (int ni = 0; ni < 4; ni++) acc[ni] = make_float4(0.f,0.f,0.f,0.f);
#pragma unroll
        for (int ks = 0; ks < 12; ks++) {
            int kb = ks * 16;
            int dk = kb >> 6, koff = kb & 63;
            int qa = lb * 10 + g + dk;
            int qb = (lb + 1) * 10 + g + dk;
            uint32_t afr[4];
            afr[0] = lds_u32(&h2s[qa * 72 + koff + 2*tg]);
            afr[1] = lds_u32(&h2s[qb * 72 + koff + 2*tg]);
            afr[2] = lds_u32(&h2s[qa * 72 + koff + 2*tg + 8]);
            afr[3] = lds_u32(&h2s[qb * 72 + koff + 2*tg + 8]);
            uint32_t bfr[4][2];
#pragma unroll
            for (int ni = 0; ni < 4; ni++) {
                int c = n_base + ni * 8 + g;
                bfr[ni][0] = lds_u32(&c2ws[c * 200 + kb + 2*tg]);
                bfr[ni][1] = lds_u32(&c2ws[c * 200 + kb + 2*tg + 8]);
            }
#pragma unroll
            for (int ni = 0; ni < 4; ni++)
                mma_f16(acc[ni], afr, bfr[ni]);
        }
        __syncthreads();   // h2s reads + Asm long free -> safe to overwrite both

        // ---- G4: wfc2 into h2s region ----
#pragma unroll
        for (int i = 0; i < 2; i++) {
            int f = t + 256 * i;
            cp_async16(&wfh[f * 8], &g_wfc2H[f * 8]);
        }
        asm volatile("cp.async.commit_group;\n");

        int r = m_base + g;
        int n_b = n_base;
#pragma unroll
        for (int ni = 0; ni < 4; ni++) {
            int o0 = n_b + ni * 8 + 2 * tg, o1 = o0 + 1;
            float bia0 = __ldg(&c2b[o0]), bia1 = __ldg(&c2b[o1]);
            float s0 = g_bn3s[o0], t0 = g_bn3t[o0];
            float s1 = g_bn3s[o1], t1 = g_bn3t[o1];
            float4 d = acc[ni];
            h3s[r * 72 + o0] = __float2half_rn(fmaxf((d.x + bia0) * s0 + t0, 0.f));
            h3s[r * 72 + o1] = __float2half_rn(fmaxf((d.y + bia1) * s1 + t1, 0.f));
            h3s[(r + 8) * 72 + o0] = __float2half_rn(fmaxf((d.z + bia0) * s0 + t0, 0.f));
            h3s[(r + 8) * 72 + o1] = __float2half_rn(fmaxf((d.w + bia1) * s1 + t1, 0.f));
        }
    }
    asm volatile("cp.async.wait_group 1;\n");   // G3 (c3w) done
    __syncthreads();                             // h3s visible

    // ---- phase 3: c3  M64 K64 N128 + residual + relu -> ys ----
    {
        int n_base = (w >> 2) * 64;
        float4 acc[8];
#pragma unroll
        for (int ni = 0; ni < 8; ni++) acc[ni] = make_float4(0.f,0.f,0.f,0.f);
#pragma unroll
        for (int ks = 0; ks < 4; ks++) {
            int kb = ks * 16;
            uint32_t afr[4];
            int r = m_base + g;
            afr[0] = lds_u32(&h3s[r * 72 + kb + 2*tg]);
            afr[1] = lds_u32(&h3s[(r + 8) * 72 + kb + 2*tg]);
            afr[2] = lds_u32(&h3s[r * 72 + kb + 2*tg + 8]);
            afr[3] = lds_u32(&h3s[(r + 8) * 72 + kb + 2*tg + 8]);
            uint32_t bfr[8][2];
#pragma unroll
            for (int ni = 0; ni < 8; ni++) {
                int c = n_base + ni * 8 + g;
                bfr[ni][0] = lds_u32(&c3ws[c * 72 + kb + 2*tg]);
                bfr[ni][1] = lds_u32(&c3ws[c * 72 + kb + 2*tg + 8]);
            }
#pragma unroll
            for (int ni = 0; ni < 8; ni++)
                mma_f16(acc[ni], afr, bfr[ni]);
        }
        // c2ws (W2) reads finished in phase 2 (>=2 barriers ago) -> ys safe
        int r = m_base + g, r2 = r + 8;
        int l1 = lb, p1 = g;
        int l2 = lb + 1, p2 = g;
        size_t gr1 = (size_t)(r0 + r) * DLOI, gr2 = (size_t)(r0 + r2) * DLOI;
#pragma unroll
        for (int ni = 0; ni < 8; ni++) {
            int o0 = n_base + ni * 8 + 2 * tg, o1 = o0 + 1;
            float bia0 = __ldg(&c3b[o0]), bia1 = __ldg(&c3b[o1]);
            float4 d = acc[ni];
            ys[l1 * 1024 + o0 * 8 + p1] = __float2half_rn(
                fmaxf(d.x + bia0 + __half2float(__ldg(&g_xph[gr1 + o0])), 0.f));
            ys[l1 * 1024 + o1 * 8 + p1] = __float2half_rn(
                fmaxf(d.y + bia1 + __half2float(__ldg(&g_xph[gr1 + o1])), 0.f));
            ys[l2 * 1024 + o0 * 8 + p2] = __float2half_rn(
                fmaxf(d.z + bia0 + __half2float(__ldg(&g_xph[gr2 + o0])), 0.f));
            ys[l2 * 1024 + o1 * 8 + p2] = __float2half_rn(
                fmaxf(d.w + bia1 + __half2float(__ldg(&g_xph[gr2 + o1])), 0.f));
        }
    }
    asm volatile("cp.async.wait_group 0;\n");   // G4 (wfc2) done
    __syncthreads();                             // ys + wfh visible

    // ---- phase 4: fc2 + softmax, warp per line ----
    {
        const __half* Y = ys + w * 1024;
        float s0 = 0.f, s1 = 0.f, s2 = 0.f, s3 = 0.f;
#pragma unroll
        for (int j = 0; j < 8; j++) {
            int idx = lane * 4 + j * 128;
            float2 ya = __half22float2(*(const __half2*)&Y[idx]);
            float2 yb = __half22float2(*(const __half2*)&Y[idx + 2]);
            float2 w0a = __half22float2(*(const __half2*)&wfh[idx]);
            float2 w0b = __half22float2(*(const __half2*)&wfh[idx + 2]);
            float2 w1a = __half22float2(*(const __half2*)&wfh[1024 + idx]);
            float2 w1b = __half22float2(*(const __half2*)&wfh[1024 + idx + 2]);
            float2 w2a = __half22float2(*(const __half2*)&wfh[2048 + idx]);
            float2 w2b = __half22float2(*(const __half2*)&wfh[2048 + idx + 2]);
            float2 w3a = __half22float2(*(const __half2*)&wfh[3072 + idx]);
            float2 w3b = __half22float2(*(const __half2*)&wfh[3072 + idx + 2]);
            s0 += ya.x * w0a.x + ya.y * w0a.y + yb.x * w0b.x + yb.y * w0b.y;
            s1 += ya.x * w1a.x + ya.y * w1a.y + yb.x * w1b.x + yb.y * w1b.y;
            s2 += ya.x * w2a.x + ya.y * w2a.y + yb.x * w2b.x + yb.y * w2b.y;
            s3 += ya.x * w3a.x + ya.y * w3a.y + yb.x * w3b.x + yb.y * w3b.y;
        }
#pragma unroll
        for (int off = 16; off; off >>= 1) {
            s0 += __shfl_down_sync(0xffffffffu, s0, off);
            s1 += __shfl_down_sync(0xffffffffu, s1, off);
            s2 += __shfl_down_sync(0xffffffffu, s2, off);
            s3 += __shfl_down_sync(0xffffffffu, s3, off);
        }
        if (lane == 0) {
            int n = blockIdx.x * 8 + w;
            float z0 = s0 + __ldg(&bfc2[0]), z1 = s1 + __ldg(&bfc2[1]);
            float z2 = s2 + __ldg(&bfc2[2]), z3 = s3 + __ldg(&bfc2[3]);
            float m = fmaxf(fmaxf(z0, z1), fmaxf(z2, z3));
            float e0 = expf(z0 - m), e1 = expf(z1 - m), e2 = expf(z2 - m), e3 = expf(z3 - m);
            float inv = 1.0f / (e0 + e1 + e2 + e3);
            *(float4*)&out[(size_t)n * 4] = make_float4(e0 * inv, e1 * inv, e2 * inv, e3 * inv);
        }
    }
}

// ---------------- launch ----------------
extern "C" void kernel_launch(void* const* d_in, const int* in_sizes, int n_in,
                              void* d_out, int out_size)
{
    const float* feature = (const float*)d_in[0];
    const float* lines   = (const float*)d_in[1];
    const float* w_fc1   = (const float*)d_in[2];
    const float* b_fc1   = (const float*)d_in[3];
    const float* bn1     = (const float*)d_in[4];
    const float* c1_w    = (const float*)d_in[5];
    const float* c1_b    = (const float*)d_in[6];
    const float* bn2     = (const float*)d_in[7];
    const float* c2_w    = (const float*)d_in[8];
    const float* c2_b    = (const float*)d_in[9];
    const float* bn3     = (const float*)d_in[10];
    const float* c3_w    = (const float*)d_in[11];
    const float* c3_b    = (const float*)d_in[12];
    const float* w_fc2   = (const float*)d_in[13];
    const float* b_fc2   = (const float*)d_in[14];
    float* out = (float*)d_out;

    static int attr_set = 0;
    if (!attr_set) {
        cudaFuncSetAttribute(fc1_gemm_tf32, cudaFuncAttributeMaxDynamicSharedMemorySize, FC1_SMEM);
        cudaFuncSetAttribute(bottleneck_fused, cudaFuncAttributeMaxDynamicSharedMemorySize, FB_SMEM);
        attr_set = 1;
    }

    prep_kernel<<<64, 256>>>(w_fc1, bn1, c1_w, bn2, c2_w, bn3, c3_w, w_fc2);

    dim3 grid(HW / 256, BQ);
    fc1_gemm_tf32<<<grid, 256, FC1_SMEM>>>(feature, b_fc1);

    line_gather<<<NL, 128>>>(lines);
    bottleneck_fused<<<RROWS / 64, 256, FB_SMEM>>>(c1_b, c2_b, c3_b, b_fc2, out);
}

// round 17
// speedup vs baseline: 1.3554x; 1.0166x over previous
#include <cuda_runtime.h>
#include <cuda_fp16.h>
#include <stdint.h>
#include <math.h>

#define BQ 2
#define LQ 5000
#define NL (BQ*LQ)
#define RROWS (NL*8)
#define CIN 256
#define DLOI 128
#define NPTS0 32
#define NPTS1 8
#define HH 256
#define HALF 64
#define HW (HH*HH)
#define EPSBN 1e-5f

// ---------------- scratch (device globals; no allocation allowed) ----------------
__device__ __half g_xh[BQ * HW * DLOI];        // fc1 output, NHWC, fp16 (33.5 MB)
__device__ float g_wfc1T[CIN * DLOI];          // [k][o], tf32-rounded (fc1 B operand)
__device__ __half g_c1wH[HALF * DLOI];         // [o][k=c]
__device__ __half g_c2wH[HALF * 192];          // [o][k=dk*64+i]
__device__ __half g_c3wH[DLOI * HALF];         // [o][k=i]
__device__ __half g_wfc2H[4 * DLOI * NPTS1];   // [q][c*8+p] fp16
__device__ float g_bn1s[DLOI], g_bn1t[DLOI];
__device__ float g_bn2s[HALF], g_bn2t[HALF];
__device__ float g_bn3s[HALF], g_bn3t[HALF];
__device__ __half g_xph[RROWS * DLOI];         // raw pooled residual

__device__ __forceinline__ float to_tf32(float x) {
    uint32_t r;
    asm("cvt.rna.tf32.f32 %0, %1;" : "=r"(r) : "f"(x));
    return __uint_as_float(r);
}

// ---------------- prep: convert weights, fold BN ----------------
__global__ void prep_kernel(const float* __restrict__ w_fc1,
                            const float* __restrict__ bn1,
                            const float* __restrict__ c1w,
                            const float* __restrict__ bn2,
                            const float* __restrict__ c2w,
                            const float* __restrict__ bn3,
                            const float* __restrict__ c3w,
                            const float* __restrict__ wfc2)
{
    int t = blockIdx.x * blockDim.x + threadIdx.x;
    int stride = gridDim.x * blockDim.x;
    for (int idx = t; idx < DLOI * CIN; idx += stride) {
        int o = idx / CIN, k = idx % CIN;
        g_wfc1T[k * DLOI + o] = to_tf32(w_fc1[idx]);
    }
    for (int idx = t; idx < HALF * DLOI; idx += stride) {
        g_c1wH[idx] = __float2half_rn(c1w[idx]);
    }
    for (int idx = t; idx < HALF * HALF * 3; idx += stride) {
        int o = idx / (HALF * 3), rem = idx % (HALF * 3);
        int i = rem / 3, dk = rem % 3;
        g_c2wH[o * 192 + dk * HALF + i] = __float2half_rn(c2w[idx]);
    }
    for (int idx = t; idx < DLOI * HALF; idx += stride) {
        g_c3wH[idx] = __float2half_rn(c3w[idx]);
    }
    for (int idx = t; idx < 4 * DLOI * NPTS1; idx += stride) {
        g_wfc2H[idx] = __float2half_rn(wfc2[idx]);
    }
    for (int idx = t; idx < DLOI; idx += stride) {
        float g = bn1[idx], be = bn1[DLOI + idx], mu = bn1[2*DLOI + idx], va = bn1[3*DLOI + idx];
        float s = g * rsqrtf(va + EPSBN);
        g_bn1s[idx] = s; g_bn1t[idx] = be - mu * s;
    }
    for (int idx = t; idx < HALF; idx += stride) {
        float g = bn2[idx], be = bn2[HALF + idx], mu = bn2[2*HALF + idx], va = bn2[3*HALF + idx];
        float s = g * rsqrtf(va + EPSBN);
        g_bn2s[idx] = s; g_bn2t[idx] = be - mu * s;
        float g3 = bn3[idx], be3 = bn3[HALF + idx], mu3 = bn3[2*HALF + idx], va3 = bn3[3*HALF + idx];
        float s3 = g3 * rsqrtf(va3 + EPSBN);
        g_bn3s[idx] = s3; g_bn3t[idx] = be3 - mu3 * s3;
    }
}

// ---------------- MMA helpers ----------------
__device__ __forceinline__ void cp_async16(void* smem_ptr, const void* gmem_ptr) {
    uint32_t s = (uint32_t)__cvta_generic_to_shared(smem_ptr);
    asm volatile("cp.async.cg.shared.global [%0], [%1], 16;\n" :: "r"(s), "l"(gmem_ptr));
}

__device__ __forceinline__ void mma_tf32(float4& d, const float* a, const float* b) {
    asm volatile(
        "mma.sync.aligned.m16n8k8.row.col.f32.tf32.tf32.f32 "
        "{%0,%1,%2,%3}, {%4,%5,%6,%7}, {%8,%9}, {%0,%1,%2,%3};\n"
        : "+f"(d.x), "+f"(d.y), "+f"(d.z), "+f"(d.w)
        : "r"(__float_as_uint(a[0])), "r"(__float_as_uint(a[1])),
          "r"(__float_as_uint(a[2])), "r"(__float_as_uint(a[3])),
          "r"(__float_as_uint(b[0])), "r"(__float_as_uint(b[1])));
}

__device__ __forceinline__ void mma_f16(float4& d, const uint32_t* a, const uint32_t* b) {
    asm volatile(
        "mma.sync.aligned.m16n8k16.row.col.f32.f16.f16.f32 "
        "{%0,%1,%2,%3}, {%4,%5,%6,%7}, {%8,%9}, {%0,%1,%2,%3};\n"
        : "+f"(d.x), "+f"(d.y), "+f"(d.z), "+f"(d.w)
        : "r"(a[0]), "r"(a[1]), "r"(a[2]), "r"(a[3]), "r"(b[0]), "r"(b[1]));
}

__device__ __forceinline__ uint32_t lds_u32(const __half* p) {
    return *(const uint32_t*)p;
}

// ---------------- fc1 GEMM: BM=256 x BN=128, tf32 mma.sync + cp.async ----------
#define KT 32
#define ASTR 260
#define BSTR 132
#define OSH 136
#define STAGE_FLOATS (KT * ASTR + KT * BSTR)
#define FC1_SMEM (2 * STAGE_FLOATS * 4)

__global__ __launch_bounds__(256) void fc1_gemm_tf32(const float* __restrict__ feat,
                                                     const float* __restrict__ bfc1)
{
    extern __shared__ float sm[];

    int b  = blockIdx.y;
    int p0 = blockIdx.x * 256;
    const float* A = feat + (size_t)b * CIN * HW;
    __half* O = g_xh + (size_t)b * HW * DLOI;

    int t    = threadIdx.x;
    int w    = t >> 5;
    int lane = t & 31;
    int g    = lane >> 2;
    int tg   = lane & 3;
    int warp_m = w & 3;
    int warp_n = w >> 2;
    int m_base = warp_m * 64;
    int n_base = warp_n * 64;

    float4 acc[4][8];
#pragma unroll
    for (int mi = 0; mi < 4; mi++)
#pragma unroll
        for (int ni = 0; ni < 8; ni++) acc[mi][ni] = make_float4(0.f, 0.f, 0.f, 0.f);

    auto issue_stage = [&](int s) {
        float* As = sm + (s & 1) * STAGE_FLOATS;
        float* Bs = As + KT * ASTR;
        int k0 = s * KT;
#pragma unroll
        for (int i = 0; i < 8; i++) {
            int f  = t + 256 * i;
            int kk = f >> 6;
            int pm = (f & 63) * 4;
            cp_async16(&As[kk * ASTR + pm], &A[(size_t)(k0 + kk) * HW + p0 + pm]);
        }
#pragma unroll
        for (int i = 0; i < 4; i++) {
            int f  = t + 256 * i;
            int kk = f >> 5;
            int pm = (f & 31) * 4;
            cp_async16(&Bs[kk * BSTR + pm], &g_wfc1T[(k0 + kk) * DLOI + pm]);
        }
        asm volatile("cp.async.commit_group;\n");
    };

    issue_stage(0);

    const int NS = CIN / KT;
    for (int s = 0; s < NS; s++) {
        if (s + 1 < NS) {
            issue_stage(s + 1);
            asm volatile("cp.async.wait_group 1;\n");
        } else {
            asm volatile("cp.async.wait_group 0;\n");
        }
        __syncthreads();

        float* As = sm + (s & 1) * STAGE_FLOATS;
        float* Bs = As + KT * ASTR;

#pragma unroll
        for (int ks = 0; ks < KT / 8; ks++) {
            int kb = ks * 8;
            float afr[4][4];
#pragma unroll
            for (int mi = 0; mi < 4; mi++) {
                int r = m_base + mi * 16 + g;
                afr[mi][0] = As[(kb + tg) * ASTR + r];
                afr[mi][1] = As[(kb + tg) * ASTR + r + 8];
                afr[mi][2] = As[(kb + tg + 4) * ASTR + r];
                afr[mi][3] = As[(kb + tg + 4) * ASTR + r + 8];
            }
            float bfr[8][2];
#pragma unroll
            for (int ni = 0; ni < 8; ni++) {
                int c = n_base + ni * 8 + g;
                bfr[ni][0] = Bs[(kb + tg) * BSTR + c];
                bfr[ni][1] = Bs[(kb + tg + 4) * BSTR + c];
            }
#pragma unroll
            for (int mi = 0; mi < 4; mi++)
#pragma unroll
                for (int ni = 0; ni < 8; ni++)
                    mma_tf32(acc[mi][ni], afr[mi], bfr[ni]);
        }
        __syncthreads();
    }

    float bx[8], by[8];
#pragma unroll
    for (int ni = 0; ni < 8; ni++) {
        int c = n_base + ni * 8 + 2 * tg;
        bx[ni] = bfc1[c];
        by[ni] = bfc1[c + 1];
    }

    __half* Osm = (__half*)sm;
#pragma unroll
    for (int chunk = 0; chunk < 4; chunk++) {
        if (warp_m == chunk) {
#pragma unroll
            for (int mi = 0; mi < 4; mi++) {
#pragma unroll
                for (int ni = 0; ni < 8; ni++) {
                    int row = mi * 16 + g;
                    int col = n_base + ni * 8 + 2 * tg;
                    float4 d = acc[mi][ni];
                    *(__half2*)&Osm[row * OSH + col] =
                        __floats2half2_rn(d.x + bx[ni], d.y + by[ni]);
                    *(__half2*)&Osm[(row + 8) * OSH + col] =
                        __floats2half2_rn(d.z + bx[ni], d.w + by[ni]);
                }
            }
        }
        __syncthreads();
#pragma unroll
        for (int i = 0; i < 4; i++) {
            int f   = t + 256 * i;
            int row = f >> 4;
            int h0  = (f & 15) * 8;
            uint4 v = *(const uint4*)&Osm[row * OSH + h0];
            *(uint4*)&O[(size_t)(p0 + chunk * 64 + row) * DLOI + h0] = v;
        }
        __syncthreads();
    }
}

// ---------------- fused gather + bottleneck + fc2 + softmax: 8 lines per CTA ----
// smem (halves), phase-overlaid:
//  Asm [64][136] 8704  : gather h1 + phase1 A; phase2+ h3s [64][72]
//  h2s [80][72]  5760  : phase1/2 h2; phase4 wfh[4096]
//  W1  9216            : c1w [64][136] (phase1); c3w [128][72] (phase3)
//  W2  12800           : gather geometry soff/swt (8KB); c2w [64][200] (phase2); ys [8][1024] (phase3+)
#define FB_A    0
#define FB_H2   8704
#define FB_W1   (FB_H2 + 5760)
#define FB_W2   (FB_W1 + 9216)
#define FB_TOT  (FB_W2 + 12800)
#define FB_SMEM (FB_TOT * 2)

__global__ __launch_bounds__(256) void bottleneck_fused(const float* __restrict__ lines,
                                                        const float* __restrict__ c1b,
                                                        const float* __restrict__ c2b,
                                                        const float* __restrict__ c3b,
                                                        const float* __restrict__ bfc2,
                                                        float* __restrict__ out)
{
    extern __shared__ __half smh[];
    __half* Asm  = smh + FB_A;
    __half* h2s  = smh + FB_H2;
    __half* c1ws = smh + FB_W1;    // stride 136
    __half* c3ws = smh + FB_W1;    // stride 72 (phase 3)
    __half* c2ws = smh + FB_W2;    // stride 200 (phase 2)
    __half* ys   = smh + FB_W2;    // [8][1024] (phase 3+)
    __half* wfh  = smh + FB_H2;    // [4096] (phase 4)
    __half* h3s  = smh + FB_A;     // stride 72 (phase 2+)
    int4*   soffs = (int4*)(smh + FB_W2);          // [8][32]
    float4* swts  = (float4*)(smh + FB_W2 + 2048); // [8][32]

    int r0 = blockIdx.x * 64;
    int t = threadIdx.x;
    int w = t >> 5, lane = t & 31, g = lane >> 2, tg = lane & 3;
    int m_base = (w & 3) * 16;
    int lb = m_base >> 3;

    // ---- G1: c1w ----
#pragma unroll
    for (int i = 0; i < 4; i++) {
        int f = t + 256 * i;
        int row = f >> 4, c8 = (f & 15) * 8;
        cp_async16(&c1ws[row * 136 + c8], &g_c1wH[row * DLOI + c8]);
    }
    asm volatile("cp.async.commit_group;\n");

    // ---- phase 0a: geometry (one sample per thread) ----
    {
        int lg = t >> 5, k = t & 31;
        int n = blockIdx.x * 8 + lg;
        const float* ln = lines + (size_t)n * 4;
        float ax = __ldg(ln), ay = __ldg(ln + 1), bx = __ldg(ln + 2), by = __ldg(ln + 3);
        float lam = (float)k * (1.0f / 31.0f);
        float px = ax * lam + bx * (1.0f - lam) - 0.5f;
        float py = ay * lam + by * (1.0f - lam) - 0.5f;
        float px0 = fminf(fmaxf(floorf(px), 0.0f), 255.0f);
        float py0 = fminf(fmaxf(floorf(py), 0.0f), 255.0f);
        float px1 = fminf(px0 + 1.0f, 255.0f);
        float py1 = fminf(py0 + 1.0f, 255.0f);
        int i0 = (int)px0, j0 = (int)py0, i1 = (int)px1, j1 = (int)py1;
        float w00 = (px1 - px) * (py1 - py);
        float w10 = (px - px0) * (py1 - py);
        float w01 = (px1 - px) * (py - py0);
        float w11 = (px - px0) * (py - py0);
        soffs[lg * 32 + k] = make_int4(((i0 << 8) + j0) << 6, ((i1 << 8) + j0) << 6,
                                       ((i0 << 8) + j1) << 6, ((i1 << 8) + j1) << 6);
        swts[lg * 32 + k] = make_float4(w00, w10, w01, w11);
    }
    // zero h2s pad rows (16 rows x 72 halves = 576 u32)
    for (int i = t; i < 576; i += 256) {
        int pr = i / 36, word = i % 36;
        int q = (pr >> 1) * 10 + (pr & 1) * 9;
        ((uint32_t*)&h2s[q * 72])[word] = 0;
    }
    __syncthreads();

    // ---- phase 0b: gather (thread = (c2, q); 2 lines x 8 points) ----
    {
        int c2 = t & 63, q = t >> 6;
        int ca = 2 * c2, cb = ca + 1;
        float sa = g_bn1s[ca], ta = g_bn1t[ca];
        float sb = g_bn1s[cb], tb = g_bn1t[cb];
#pragma unroll
        for (int lp = 0; lp < 2; lp++) {
            int lg = q * 2 + lp;
            int n = blockIdx.x * 8 + lg;
            int b = n / LQ;
            const __half2* X2 = (const __half2*)g_xh + (size_t)b * HW * 64 + c2;
#pragma unroll 2
            for (int p = 0; p < 8; p++) {
                float2 m = make_float2(-INFINITY, -INFINITY);
#pragma unroll
                for (int kk = 0; kk < 4; kk++) {
                    int k = p * 4 + kk;
                    int4  o4 = soffs[lg * 32 + k];
                    float4 w4 = swts[lg * 32 + k];
                    float2 h00 = __half22float2(__ldg(X2 + o4.x));
                    float2 h10 = __half22float2(__ldg(X2 + o4.y));
                    float2 h01 = __half22float2(__ldg(X2 + o4.z));
                    float2 h11 = __half22float2(__ldg(X2 + o4.w));
                    float vx = h00.x * w4.x + h10.x * w4.y + h01.x * w4.z + h11.x * w4.w;
                    float vy = h00.y * w4.x + h10.y * w4.y + h01.y * w4.z + h11.y * w4.w;
                    m.x = fmaxf(m.x, vx);
                    m.y = fmaxf(m.y, vy);
                }
                int row = lg * 8 + p;
                *(__half2*)&g_xph[((size_t)n * 8 + p) * DLOI + ca] = __floats2half2_rn(m.x, m.y);
                *(__half2*)&Asm[row * 136 + ca] = __floats2half2_rn(
                    fmaxf(m.x * sa + ta, 0.f), fmaxf(m.y * sb + tb, 0.f));
            }
        }
    }
    __syncthreads();   // Asm(h1) ready; geometry (W2) dead

    // ---- G2: c2w into W2 ----
#pragma unroll
    for (int i = 0; i < 6; i++) {
        int f = t + 256 * i;
        int row = f / 24, c8 = (f % 24) * 8;
        cp_async16(&c2ws[row * 200 + c8], &g_c2wH[row * 192 + c8]);
    }
    asm volatile("cp.async.commit_group;\n");
    asm volatile("cp.async.wait_group 1;\n");   // G1 (c1w) done
    __syncthreads();

    // ---- phase 1: c1  M64 K128 N64 -> h2s ----
    {
        int n_base = (w >> 2) * 32;
        float4 acc[4];
#pragma unroll
        for (int ni = 0; ni < 4; ni++) acc[ni] = make_float4(0.f,0.f,0.f,0.f);
#pragma unroll
        for (int ks = 0; ks < 8; ks++) {
            int kb = ks * 16;
            uint32_t afr[4];
            int r = m_base + g;
            afr[0] = lds_u32(&Asm[r * 136 + kb + 2*tg]);
            afr[1] = lds_u32(&Asm[(r + 8) * 136 + kb + 2*tg]);
            afr[2] = lds_u32(&Asm[r * 136 + kb + 2*tg + 8]);
            afr[3] = lds_u32(&Asm[(r + 8) * 136 + kb + 2*tg + 8]);
            uint32_t bfr[4][2];
#pragma unroll
            for (int ni = 0; ni < 4; ni++) {
                int c = n_base + ni * 8 + g;
                bfr[ni][0] = lds_u32(&c1ws[c * 136 + kb + 2*tg]);
                bfr[ni][1] = lds_u32(&c1ws[c * 136 + kb + 2*tg + 8]);
            }
#pragma unroll
            for (int ni = 0; ni < 4; ni++)
                mma_f16(acc[ni], afr, bfr[ni]);
        }
        int q1 = lb * 10 + g + 1;
        int q2 = (lb + 1) * 10 + g + 1;
#pragma unroll
        for (int ni = 0; ni < 4; ni++) {
            int o0 = n_base + ni * 8 + 2 * tg, o1 = o0 + 1;
            float bia0 = __ldg(&c1b[o0]), bia1 = __ldg(&c1b[o1]);
            float s0 = g_bn2s[o0], t0 = g_bn2t[o0];
            float s1 = g_bn2s[o1], t1 = g_bn2t[o1];
            float4 d = acc[ni];
            h2s[q1 * 72 + o0] = __float2half_rn(fmaxf((d.x + bia0) * s0 + t0, 0.f));
            h2s[q1 * 72 + o1] = __float2half_rn(fmaxf((d.y + bia1) * s1 + t1, 0.f));
            h2s[q2 * 72 + o0] = __float2half_rn(fmaxf((d.z + bia0) * s0 + t0, 0.f));
            h2s[q2 * 72 + o1] = __float2half_rn(fmaxf((d.w + bia1) * s1 + t1, 0.f));
        }
    }
    __syncthreads();   // h2s visible; c1w reads done -> W1 free

    // ---- G3: c3w into W1 (stride 72) ----
#pragma unroll
    for (int i = 0; i < 4; i++) {
        int f = t + 256 * i;
        int row = f >> 3, c8 = (f & 7) * 8;
        cp_async16(&c3ws[row * 72 + c8], &g_c3wH[row * HALF + c8]);
    }
    asm volatile("cp.async.commit_group;\n");
    asm volatile("cp.async.wait_group 1;\n");   // G2 (c2w) done
    __syncthreads();

    // ---- phase 2: c2  M64 K192 N64 ----
    {
        int n_base = (w >> 2) * 32;
        float4 acc[4];
#pragma unroll
        for (int ni = 0; ni < 4; ni++) acc[ni] = make_float4(0.f,0.f,0.f,0.f);
#pragma unroll
        for (int ks = 0; ks < 12; ks++) {
            int kb = ks * 16;
            int dk = kb >> 6, koff = kb & 63;
            int qa = lb * 10 + g + dk;
            int qb = (lb + 1) * 10 + g + dk;
            uint32_t afr[4];
            afr[0] = lds_u32(&h2s[qa * 72 + koff + 2*tg]);
            afr[1] = lds_u32(&h2s[qb * 72 + koff + 2*tg]);
            afr[2] = lds_u32(&h2s[qa * 72 + koff + 2*tg + 8]);
            afr[3] = lds_u32(&h2s[qb * 72 + koff + 2*tg + 8]);
            uint32_t bfr[4][2];
#pragma unroll
            for (int ni = 0; ni < 4; ni++) {
                int c = n_base + ni * 8 + g;
                bfr[ni][0] = lds_u32(&c2ws[c * 200 + kb + 2*tg]);
                bfr[ni][1] = lds_u32(&c2ws[c * 200 + kb + 2*tg + 8]);
            }
#pragma unroll
            for (int ni = 0; ni < 4; ni++)
                mma_f16(acc[ni], afr, bfr[ni]);
        }
        __syncthreads();   // h2s reads done; Asm reads long done

        // ---- G4: wfc2 into h2s region ----
#pragma unroll
        for (int i = 0; i < 2; i++) {
            int f = t + 256 * i;
            cp_async16(&wfh[f * 8], &g_wfc2H[f * 8]);
        }
        asm volatile("cp.async.commit_group;\n");

        int r = m_base + g;
#pragma unroll
        for (int ni = 0; ni < 4; ni++) {
            int o0 = n_base + ni * 8 + 2 * tg, o1 = o0 + 1;
            float bia0 = __ldg(&c2b[o0]), bia1 = __ldg(&c2b[o1]);
            float s0 = g_bn3s[o0], t0 = g_bn3t[o0];
            float s1 = g_bn3s[o1], t1 = g_bn3t[o1];
            float4 d = acc[ni];
            h3s[r * 72 + o0] = __float2half_rn(fmaxf((d.x + bia0) * s0 + t0, 0.f));
            h3s[r * 72 + o1] = __float2half_rn(fmaxf((d.y + bia1) * s1 + t1, 0.f));
            h3s[(r + 8) * 72 + o0] = __float2half_rn(fmaxf((d.z + bia0) * s0 + t0, 0.f));
            h3s[(r + 8) * 72 + o1] = __float2half_rn(fmaxf((d.w + bia1) * s1 + t1, 0.f));
        }
    }
    asm volatile("cp.async.wait_group 1;\n");   // G3 (c3w) done
    __syncthreads();                             // h3s visible

    // ---- phase 3: c3  M64 K64 N128 + residual + relu -> ys ----
    {
        int n_base = (w >> 2) * 64;
        float4 acc[8];
#pragma unroll
        for (int ni = 0; ni < 8; ni++) acc[ni] = make_float4(0.f,0.f,0.f,0.f);
#pragma unroll
        for (int ks = 0; ks < 4; ks++) {
            int kb = ks * 16;
            uint32_t afr[4];
            int r = m_base + g;
            afr[0] = lds_u32(&h3s[r * 72 + kb + 2*tg]);
            afr[1] = lds_u32(&h3s[(r + 8) * 72 + kb + 2*tg]);
            afr[2] = lds_u32(&h3s[r * 72 + kb + 2*tg + 8]);
            afr[3] = lds_u32(&h3s[(r + 8) * 72 + kb + 2*tg + 8]);
            uint32_t bfr[8][2];
#pragma unroll
            for (int ni = 0; ni < 8; ni++) {
                int c = n_base + ni * 8 + g;
                bfr[ni][0] = lds_u32(&c3ws[c * 72 + kb + 2*tg]);
                bfr[ni][1] = lds_u32(&c3ws[c * 72 + kb + 2*tg + 8]);
            }
#pragma unroll
            for (int ni = 0; ni < 8; ni++)
                mma_f16(acc[ni], afr, bfr[ni]);
        }
        int r = m_base + g, r2 = r + 8;
        int l1 = lb, p1 = g;
        int l2 = lb + 1, p2 = g;
        size_t gr1 = (size_t)(r0 + r) * DLOI, gr2 = (size_t)(r0 + r2) * DLOI;
#pragma unroll
        for (int ni = 0; ni < 8; ni++) {
            int o0 = n_base + ni * 8 + 2 * tg, o1 = o0 + 1;
            float bia0 = __ldg(&c3b[o0]), bia1 = __ldg(&c3b[o1]);
            float4 d = acc[ni];
            ys[l1 * 1024 + o0 * 8 + p1] = __float2half_rn(
                fmaxf(d.x + bia0 + __half2float(__ldg(&g_xph[gr1 + o0])), 0.f));
            ys[l1 * 1024 + o1 * 8 + p1] = __float2half_rn(
                fmaxf(d.y + bia1 + __half2float(__ldg(&g_xph[gr1 + o1])), 0.f));
            ys[l2 * 1024 + o0 * 8 + p2] = __float2half_rn(
                fmaxf(d.z + bia0 + __half2float(__ldg(&g_xph[gr2 + o0])), 0.f));
            ys[l2 * 1024 + o1 * 8 + p2] = __float2half_rn(
                fmaxf(d.w + bia1 + __half2float(__ldg(&g_xph[gr2 + o1])), 0.f));
        }
    }
    asm volatile("cp.async.wait_group 0;\n");   // G4 (wfc2) done
    __syncthreads();                             // ys + wfh visible

    // ---- phase 4: fc2 + softmax, warp per line ----
    {
        const __half* Y = ys + w * 1024;
        float s0 = 0.f, s1 = 0.f, s2 = 0.f, s3 = 0.f;
#pragma unroll
        for (int j = 0; j < 8; j++) {
            int idx = lane * 4 + j * 128;
            float2 ya = __half22float2(*(const __half2*)&Y[idx]);
            float2 yb = __half22float2(*(const __half2*)&Y[idx + 2]);
            float2 w0a = __half22float2(*(const __half2*)&wfh[idx]);
            float2 w0b = __half22float2(*(const __half2*)&wfh[idx + 2]);
            float2 w1a = __half22float2(*(const __half2*)&wfh[1024 + idx]);
            float2 w1b = __half22float2(*(const __half2*)&wfh[1024 + idx + 2]);
            float2 w2a = __half22float2(*(const __half2*)&wfh[2048 + idx]);
            float2 w2b = __half22float2(*(const __half2*)&wfh[2048 + idx + 2]);
            float2 w3a = __half22float2(*(const __half2*)&wfh[3072 + idx]);
            float2 w3b = __half22float2(*(const __half2*)&wfh[3072 + idx + 2]);
            s0 += ya.x * w0a.x + ya.y * w0a.y + yb.x * w0b.x + yb.y * w0b.y;
            s1 += ya.x * w1a.x + ya.y * w1a.y + yb.x * w1b.x + yb.y * w1b.y;
            s2 += ya.x * w2a.x + ya.y * w2a.y + yb.x * w2b.x + yb.y * w2b.y;
            s3 += ya.x * w3a.x + ya.y * w3a.y + yb.x * w3b.x + yb.y * w3b.y;
        }
#pragma unroll
        for (int off = 16; off; off >>= 1) {
            s0 += __shfl_down_sync(0xffffffffu, s0, off);
            s1 += __shfl_down_sync(0xffffffffu, s1, off);
            s2 += __shfl_down_sync(0xffffffffu, s2, off);
            s3 += __shfl_down_sync(0xffffffffu, s3, off);
        }
        if (lane == 0) {
            int n = blockIdx.x * 8 + w;
            float z0 = s0 + __ldg(&bfc2[0]), z1 = s1 + __ldg(&bfc2[1]);
            float z2 = s2 + __ldg(&bfc2[2]), z3 = s3 + __ldg(&bfc2[3]);
            float m = fmaxf(fmaxf(z0, z1), fmaxf(z2, z3));
            float e0 = expf(z0 - m), e1 = expf(z1 - m), e2 = expf(z2 - m), e3 = expf(z3 - m);
            float inv = 1.0f / (e0 + e1 + e2 + e3);
            *(float4*)&out[(size_t)n * 4] = make_float4(e0 * inv, e1 * inv, e2 * inv, e3 * inv);
        }
    }
}

// ---------------- launch ----------------
extern "C" void kernel_launch(void* const* d_in, const int* in_sizes, int n_in,
                              void* d_out, int out_size)
{
    const float* feature = (const float*)d_in[0];
    const float* lines   = (const float*)d_in[1];
    const float* w_fc1   = (const float*)d_in[2];
    const float* b_fc1   = (const float*)d_in[3];
    const float* bn1     = (const float*)d_in[4];
    const float* c1_w    = (const float*)d_in[5];
    const float* c1_b    = (const float*)d_in[6];
    const float* bn2     = (const float*)d_in[7];
    const float* c2_w    = (const float*)d_in[8];
    const float* c2_b    = (const float*)d_in[9];
    const float* bn3     = (const float*)d_in[10];
    const float* c3_w    = (const float*)d_in[11];
    const float* c3_b    = (const float*)d_in[12];
    const float* w_fc2   = (const float*)d_in[13];
    const float* b_fc2   = (const float*)d_in[14];
    float* out = (float*)d_out;

    static int attr_set = 0;
    if (!attr_set) {
        cudaFuncSetAttribute(fc1_gemm_tf32, cudaFuncAttributeMaxDynamicSharedMemorySize, FC1_SMEM);
        cudaFuncSetAttribute(bottleneck_fused, cudaFuncAttributeMaxDynamicSharedMemorySize, FB_SMEM);
        attr_set = 1;
    }

    prep_kernel<<<64, 256>>>(w_fc1, bn1, c1_w, bn2, c2_w, bn3, c3_w, w_fc2);

    dim3 grid(HW / 256, BQ);
    fc1_gemm_tf32<<<grid, 256, FC1_SMEM>>>(feature, b_fc1);

    bottleneck_fused<<<NL / 8, 256, FB_SMEM>>>(lines, c1_b, c2_b, c3_b, b_fc2, out);
}